// round 2
// baseline (speedup 1.0000x reference)
#include <cuda_runtime.h>
#include <math.h>

// ---------------- scratch (128 MB each) ----------------
__device__ float g_qk[65536ull * 512];   // [b][h*128 + c]
__device__ float g_ctx[65536ull * 512];  // [b][h*128 + c]

__device__ __forceinline__ float sigm(float z) {
    return 1.0f / (1.0f + __expf(-z));
}

// =======================================================================
// K1: qk[b][h][c] = sum_d q[b][h*32+d] * Wk[h*32+d][c],  q = Wq x + bq
// 64 rows/block, 256 threads. Dynamic smem:
//   sW  [128][132]  (Wq padded; reused for Wk natural [128][128])
//   sX  [64][128]
//   sQ  [64][128]
// =======================================================================
#define K1_SMEM_FLOATS (128*132 + 64*128 + 64*128)

__global__ void __launch_bounds__(256, 1) k1_qk(
    const float* __restrict__ x,
    const float* __restrict__ Wq, const float* __restrict__ bq,
    const float* __restrict__ Wk)
{
    extern __shared__ float sm[];
    float* sW = sm;                  // 16896 floats
    float* sX = sm + 128*132;        // 8192
    float* sQ = sX + 64*128;         // 8192

    const int t = threadIdx.x;
    const int lane = t & 31;
    const int tr = t >> 5;           // warp id 0..7
    const int r0 = tr * 8;
    const long rowBase = (long)blockIdx.x * 64;

    // load Wq (padded rows of 132) and x tile
    for (int i = t; i < 128*128; i += 256) {
        int j = i >> 7, c = i & 127;
        sW[j*132 + c] = Wq[i];
    }
    {
        const float4* xg = (const float4*)(x + rowBase * 128);
        float4* sx4 = (float4*)sX;
        for (int i = t; i < 64*32; i += 256) sx4[i] = xg[i];
    }
    __syncthreads();

    // ---- stage A: q[r][j] = Wq x + bq ; j = lane + 32*jj, r = r0+rr ----
    {
        float acc[4][8];
        #pragma unroll
        for (int jj = 0; jj < 4; jj++) {
            float b = __ldg(&bq[lane + 32*jj]);
            #pragma unroll
            for (int rr = 0; rr < 8; rr++) acc[jj][rr] = b;
        }
        #pragma unroll 4
        for (int c4 = 0; c4 < 32; c4++) {
            float4 w[4];
            #pragma unroll
            for (int jj = 0; jj < 4; jj++)
                w[jj] = *(const float4*)&sW[(lane + 32*jj)*132 + c4*4];
            #pragma unroll
            for (int rr = 0; rr < 8; rr++) {
                float4 xv = *(const float4*)&sX[(r0+rr)*128 + c4*4];
                #pragma unroll
                for (int jj = 0; jj < 4; jj++) {
                    acc[jj][rr] += w[jj].x*xv.x;
                    acc[jj][rr] += w[jj].y*xv.y;
                    acc[jj][rr] += w[jj].z*xv.z;
                    acc[jj][rr] += w[jj].w*xv.w;
                }
            }
        }
        #pragma unroll
        for (int jj = 0; jj < 4; jj++)
            #pragma unroll
            for (int rr = 0; rr < 8; rr++)
                sQ[(r0+rr)*128 + lane + 32*jj] = acc[jj][rr];
    }
    __syncthreads();

    // reload: Wk natural [j][128]
    for (int i = t; i < 128*128; i += 256) sW[i] = Wk[i];
    __syncthreads();

    // ---- stage B: qk[r][h][c] = sum_d q[r][h*32+d]*Wk[h*32+d][c] ----
    // c = lane + 32*k (k=0..3), r = r0+rr, loop h
    for (int h = 0; h < 4; h++) {
        float acc[4][8];
        #pragma unroll
        for (int k = 0; k < 4; k++)
            #pragma unroll
            for (int rr = 0; rr < 8; rr++) acc[k][rr] = 0.0f;

        #pragma unroll 4
        for (int d = 0; d < 32; d++) {
            const int j = h*32 + d;
            float wv[4];
            #pragma unroll
            for (int k = 0; k < 4; k++) wv[k] = sW[j*128 + lane + 32*k];
            #pragma unroll
            for (int rr = 0; rr < 8; rr++) {
                float qv = sQ[(r0+rr)*128 + j];
                #pragma unroll
                for (int k = 0; k < 4; k++) acc[k][rr] += wv[k] * qv;
            }
        }
        #pragma unroll
        for (int rr = 0; rr < 8; rr++)
            #pragma unroll
            for (int k = 0; k < 4; k++)
                g_qk[(rowBase + r0 + rr)*512 + h*128 + lane + 32*k] = acc[k][rr];
    }
}

// =======================================================================
// K2: attention. warp per row, 8 rows/block, neighbors streamed once.
// smem: s_nb[8][20][128]
// =======================================================================
#define K2_SMEM_FLOATS (8*20*128)

__global__ void __launch_bounds__(256) k2_attn(const float* __restrict__ nb)
{
    extern __shared__ float sm[];
    const int t = threadIdx.x;
    const int lane = t & 31;
    const int w = t >> 5;
    const long b = (long)blockIdx.x * 8 + w;

    float4* snb4 = (float4*)(sm + w * 2560);

    // qk in registers: qk4[h] holds c = lane*4 .. lane*4+3
    float4 qk4[4];
    {
        const float4* qkg = (const float4*)(g_qk + b * 512);
        #pragma unroll
        for (int h = 0; h < 4; h++) qk4[h] = qkg[h*32 + lane];
    }

    float sc[4];
    #pragma unroll
    for (int h = 0; h < 4; h++) sc[h] = -1e30f;

    const float4* nbg = (const float4*)(nb + b * 2560);

    // pass 1: scores (and stash neighbors in smem)
    for (int n = 0; n < 20; n++) {
        float4 v = nbg[n*32 + lane];
        snb4[n*32 + lane] = v;
        float p[4];
        #pragma unroll
        for (int h = 0; h < 4; h++)
            p[h] = qk4[h].x*v.x + qk4[h].y*v.y + qk4[h].z*v.z + qk4[h].w*v.w;
        #pragma unroll
        for (int o = 16; o; o >>= 1) {
            #pragma unroll
            for (int h = 0; h < 4; h++)
                p[h] += __shfl_xor_sync(0xffffffffu, p[h], o);
        }
        if (lane == n) {
            #pragma unroll
            for (int h = 0; h < 4; h++) sc[h] = p[h] * 0.17677669529663687f;
        }
    }

    // softmax across lanes 0..19 (lanes >=20 hold -1e30 -> exp underflows to 0)
    float m[4], e[4], s[4], a[4];
    #pragma unroll
    for (int h = 0; h < 4; h++) m[h] = sc[h];
    #pragma unroll
    for (int o = 16; o; o >>= 1) {
        #pragma unroll
        for (int h = 0; h < 4; h++)
            m[h] = fmaxf(m[h], __shfl_xor_sync(0xffffffffu, m[h], o));
    }
    #pragma unroll
    for (int h = 0; h < 4; h++) e[h] = __expf(sc[h] - m[h]);
    #pragma unroll
    for (int h = 0; h < 4; h++) s[h] = e[h];
    #pragma unroll
    for (int o = 16; o; o >>= 1) {
        #pragma unroll
        for (int h = 0; h < 4; h++)
            s[h] += __shfl_xor_sync(0xffffffffu, s[h], o);
    }
    #pragma unroll
    for (int h = 0; h < 4; h++) a[h] = e[h] / s[h];  // valid at lane = n

    // pass 2: ctx[h][c] = sum_n attn[h][n] * nb[n][c]
    float4 cx[4];
    #pragma unroll
    for (int h = 0; h < 4; h++) cx[h] = make_float4(0.f, 0.f, 0.f, 0.f);
    for (int n = 0; n < 20; n++) {
        float4 v = snb4[n*32 + lane];
        #pragma unroll
        for (int h = 0; h < 4; h++) {
            float ah = __shfl_sync(0xffffffffu, a[h], n);
            cx[h].x += ah * v.x; cx[h].y += ah * v.y;
            cx[h].z += ah * v.z; cx[h].w += ah * v.w;
        }
    }
    float4* cg = (float4*)(g_ctx + b * 512);
    #pragma unroll
    for (int h = 0; h < 4; h++) cg[h*32 + lane] = cx[h];
}

// =======================================================================
// K3: o = Wv ctx + bv ; permute ; o2 = Wo o + bo ; SE ; gate ; residual
// 64 rows/block, 256 threads, 231424 B dynamic smem.
// =======================================================================
#define K3_OFF_W    0                 // [128][132]  Wv padded -> later WoP padded
#define K3_OFF_CTX  16896             // [64][512]   (stage 1 only)
#define K3_OFF_O    49664             // [64][128]
#define K3_SMEM_FLOATS 57856          // 231424 bytes
// reuse of CTX region after stage 1:
#define K3_OFF_O2   16896             // [64][128]
#define K3_OFF_X    25088             // [64][128]
#define K3_OFF_T1   33280             // [64][32]
#define K3_OFF_SE1  35328             // [128][32]  Wse1T: [oc][i]
#define K3_OFF_SE2  39424             // [32][128]  Wse2T: [i][oc]
#define K3_OFF_WG   43520             // [256]
#define K3_OFF_GP   43776             // [64][4] partials + [64] gates

__global__ void __launch_bounds__(256, 1) k3_out(
    const float* __restrict__ x,
    const float* __restrict__ Wv, const float* __restrict__ bv,
    const float* __restrict__ Wo, const float* __restrict__ bo,
    const float* __restrict__ Wse1, const float* __restrict__ Wse2,
    const float* __restrict__ Wg, const float* __restrict__ bg,
    float* __restrict__ out)
{
    extern __shared__ float sm[];
    const int t = threadIdx.x;
    const int lane = t & 31;
    const int w = t >> 5;
    const long rowBase = (long)blockIdx.x * 64;

    // ---- phase 0 loads: Wv (padded), ctx tile ----
    for (int i = t; i < 128*128; i += 256) {
        int j = i >> 7, c = i & 127;
        sm[K3_OFF_W + j*132 + c] = Wv[i];
    }
    {
        const float4* cg = (const float4*)(g_ctx + rowBase * 512);
        float4* sc4 = (float4*)(sm + K3_OFF_CTX);
        for (int i = t; i < 64*128; i += 256) sc4[i] = cg[i];
    }
    __syncthreads();

    // ---- stage 1: o[r][j] = Wv[j] . ctx[r][h(j)] + bv[j] ----
    // warp w: h = w&3, rhalf = w>>2 ; lane: rgrp = lane>>3, jsub = lane&7
    // j = h*32 + jsub + 8*jj ; r = rhalf*32 + rgrp*8 + rr
    {
        const int h = w & 3, rhalf = w >> 2;
        const int rgrp = lane >> 3, jsub = lane & 7;
        const int rb = rhalf*32 + rgrp*8;
        float acc[4][8];
        #pragma unroll
        for (int jj = 0; jj < 4; jj++) {
            float b = __ldg(&bv[h*32 + jsub + 8*jj]);
            #pragma unroll
            for (int rr = 0; rr < 8; rr++) acc[jj][rr] = b;
        }
        #pragma unroll 4
        for (int c4 = 0; c4 < 32; c4++) {
            float4 wv[4];
            #pragma unroll
            for (int jj = 0; jj < 4; jj++)
                wv[jj] = *(const float4*)&sm[K3_OFF_W + (h*32 + jsub + 8*jj)*132 + c4*4];
            #pragma unroll
            for (int rr = 0; rr < 8; rr++) {
                float4 cv = *(const float4*)&sm[K3_OFF_CTX + (rb+rr)*512 + h*128 + c4*4];
                #pragma unroll
                for (int jj = 0; jj < 4; jj++) {
                    acc[jj][rr] += wv[jj].x*cv.x;
                    acc[jj][rr] += wv[jj].y*cv.y;
                    acc[jj][rr] += wv[jj].z*cv.z;
                    acc[jj][rr] += wv[jj].w*cv.w;
                }
            }
        }
        __syncthreads();   // ctx reads complete before anything overwrites; also o buffer ready
        #pragma unroll
        for (int jj = 0; jj < 4; jj++)
            #pragma unroll
            for (int rr = 0; rr < 8; rr++)
                sm[K3_OFF_O + (rb+rr)*128 + h*32 + jsub + 8*jj] = acc[jj][rr];
    }
    __syncthreads();

    // ---- phase 1 loads: WoP (permuted, padded), x, Wse1T, Wse2T, Wg ----
    for (int i = t; i < 128*128; i += 256) {
        int oc = i >> 7, j2 = i & 127;          // j2 = d*4 + h
        sm[K3_OFF_W + oc*132 + ((j2 & 3)*32 + (j2 >> 2))] = Wo[i];
    }
    {
        const float4* xg = (const float4*)(x + rowBase * 128);
        float4* sx4 = (float4*)(sm + K3_OFF_X);
        for (int i = t; i < 64*32; i += 256) sx4[i] = xg[i];
    }
    for (int i = t; i < 32*128; i += 256) {     // Wse1 [i][oc] -> [oc][i]
        int ii = i >> 7, oc = i & 127;
        sm[K3_OFF_SE1 + oc*32 + ii] = Wse1[i];
    }
    for (int i = t; i < 128*32; i += 256) {     // Wse2 [oc][i] -> [i][oc]
        int oc = i >> 5, ii = i & 31;
        sm[K3_OFF_SE2 + ii*128 + oc] = Wse2[i];
    }
    if (t < 256) sm[K3_OFF_WG + t] = Wg[t];
    __syncthreads();

    // ---- stage 2: o2[r][oc] = WoP[oc] . o[r] + bo[oc] ----
    // oc = lane + 32*jj ; r = (t>>5)*8 + rr
    {
        const int r0 = w * 8;
        float acc[4][8];
        #pragma unroll
        for (int jj = 0; jj < 4; jj++) {
            float b = __ldg(&bo[lane + 32*jj]);
            #pragma unroll
            for (int rr = 0; rr < 8; rr++) acc[jj][rr] = b;
        }
        #pragma unroll 4
        for (int c4 = 0; c4 < 32; c4++) {
            float4 wv[4];
            #pragma unroll
            for (int jj = 0; jj < 4; jj++)
                wv[jj] = *(const float4*)&sm[K3_OFF_W + (lane + 32*jj)*132 + c4*4];
            #pragma unroll
            for (int rr = 0; rr < 8; rr++) {
                float4 ov = *(const float4*)&sm[K3_OFF_O + (r0+rr)*128 + c4*4];
                #pragma unroll
                for (int jj = 0; jj < 4; jj++) {
                    acc[jj][rr] += wv[jj].x*ov.x;
                    acc[jj][rr] += wv[jj].y*ov.y;
                    acc[jj][rr] += wv[jj].z*ov.z;
                    acc[jj][rr] += wv[jj].w*ov.w;
                }
            }
        }
        #pragma unroll
        for (int jj = 0; jj < 4; jj++)
            #pragma unroll
            for (int rr = 0; rr < 8; rr++)
                sm[K3_OFF_O2 + (r0+rr)*128 + lane + 32*jj] = acc[jj][rr];
    }
    __syncthreads();

    // ---- stage 3: t1[r][i] = relu(Wse1[i] . o2[r]) ; i = lane, r = w*8+rr ----
    {
        const int r0 = w * 8;
        float acc[8];
        #pragma unroll
        for (int rr = 0; rr < 8; rr++) acc[rr] = 0.0f;
        #pragma unroll 4
        for (int oc = 0; oc < 128; oc++) {
            float wv = sm[K3_OFF_SE1 + oc*32 + lane];
            #pragma unroll
            for (int rr = 0; rr < 8; rr++)
                acc[rr] += wv * sm[K3_OFF_O2 + (r0+rr)*128 + oc];
        }
        #pragma unroll
        for (int rr = 0; rr < 8; rr++)
            sm[K3_OFF_T1 + (r0+rr)*32 + lane] = fmaxf(acc[rr], 0.0f);
    }
    __syncthreads();

    // ---- stage 4: se = sigmoid(Wse2 t1) ; o3 = o2*se (in place) ----
    {
        const int r0 = w * 8;
        float acc[4][8];
        #pragma unroll
        for (int jj = 0; jj < 4; jj++)
            #pragma unroll
            for (int rr = 0; rr < 8; rr++) acc[jj][rr] = 0.0f;
        #pragma unroll 4
        for (int i = 0; i < 32; i++) {
            float wv[4];
            #pragma unroll
            for (int jj = 0; jj < 4; jj++)
                wv[jj] = sm[K3_OFF_SE2 + i*128 + lane + 32*jj];
            #pragma unroll
            for (int rr = 0; rr < 8; rr++) {
                float tv = sm[K3_OFF_T1 + (r0+rr)*32 + i];
                #pragma unroll
                for (int jj = 0; jj < 4; jj++) acc[jj][rr] += wv[jj] * tv;
            }
        }
        #pragma unroll
        for (int jj = 0; jj < 4; jj++)
            #pragma unroll
            for (int rr = 0; rr < 8; rr++) {
                float se = sigm(acc[jj][rr]);
                sm[K3_OFF_O2 + (r0+rr)*128 + lane + 32*jj] *= se;
            }
    }
    __syncthreads();

    // ---- stage 5a: gate partials ----
    {
        const int r = t >> 2, q = t & 3;
        float p = 0.0f;
        const int base = q * 64;
        if (q < 2) {
            #pragma unroll 8
            for (int kk = 0; kk < 64; kk++)
                p += sm[K3_OFF_WG + base + kk] * sm[K3_OFF_X + r*128 + base + kk];
        } else {
            #pragma unroll 8
            for (int kk = 0; kk < 64; kk++)
                p += sm[K3_OFF_WG + base + kk] * sm[K3_OFF_O2 + r*128 + base - 128 + kk];
        }
        sm[K3_OFF_GP + r*4 + q] = p;
    }
    __syncthreads();
    // ---- stage 5b: gate ----
    if (t < 64) {
        float z = sm[K3_OFF_GP + t*4] + sm[K3_OFF_GP + t*4+1]
                + sm[K3_OFF_GP + t*4+2] + sm[K3_OFF_GP + t*4+3] + __ldg(bg);
        sm[K3_OFF_GP + 256 + t] = sigm(z);
    }
    __syncthreads();

    // ---- stage 6: out = g*o3 + (1-g)*x ----
    {
        const float4* sx4 = (const float4*)(sm + K3_OFF_X);
        const float4* so4 = (const float4*)(sm + K3_OFF_O2);
        float4* og = (float4*)(out + rowBase * 128);
        for (int i = t; i < 64*32; i += 256) {
            int r = i >> 5;
            float g = sm[K3_OFF_GP + 256 + r];
            float4 xv = sx4[i], ov = so4[i], res;
            res.x = g*ov.x + (1.0f-g)*xv.x;
            res.y = g*ov.y + (1.0f-g)*xv.y;
            res.z = g*ov.z + (1.0f-g)*xv.z;
            res.w = g*ov.w + (1.0f-g)*xv.w;
            og[i] = res;
        }
    }
}

// =======================================================================
extern "C" void kernel_launch(void* const* d_in, const int* in_sizes, int n_in,
                              void* d_out, int out_size)
{
    const float* x    = (const float*)d_in[0];
    const float* nb   = (const float*)d_in[1];
    const float* Wq   = (const float*)d_in[2];
    const float* bq   = (const float*)d_in[3];
    const float* Wk   = (const float*)d_in[4];
    // d_in[5] = bk : softmax-invariant, unused
    const float* Wv   = (const float*)d_in[6];
    const float* bv   = (const float*)d_in[7];
    const float* Wo   = (const float*)d_in[8];
    const float* bo   = (const float*)d_in[9];
    const float* Wse1 = (const float*)d_in[10];
    const float* Wse2 = (const float*)d_in[11];
    const float* Wg   = (const float*)d_in[12];
    const float* bg   = (const float*)d_in[13];
    float* out = (float*)d_out;

    static int inited = 0;
    if (!inited) {
        cudaFuncSetAttribute(k1_qk,  cudaFuncAttributeMaxDynamicSharedMemorySize, K1_SMEM_FLOATS*4);
        cudaFuncSetAttribute(k2_attn, cudaFuncAttributeMaxDynamicSharedMemorySize, K2_SMEM_FLOATS*4);
        cudaFuncSetAttribute(k3_out, cudaFuncAttributeMaxDynamicSharedMemorySize, K3_SMEM_FLOATS*4);
        inited = 1;
    }

    k1_qk<<<1024, 256, K1_SMEM_FLOATS*4>>>(x, Wq, bq, Wk);
    k2_attn<<<8192, 256, K2_SMEM_FLOATS*4>>>(nb);
    k3_out<<<1024, 256, K3_SMEM_FLOATS*4>>>(x, Wv, bv, Wo, bo, Wse1, Wse2, Wg, bg, out);
}

// round 4
// speedup vs baseline: 1.1642x; 1.1642x over previous
#include <cuda_runtime.h>
#include <math.h>

__device__ __forceinline__ float sigm(float z) {
    return 1.0f / (1.0f + __expf(-z));
}

// =======================================================================
// Fully fused kernel: 32 rows/block, 512 threads (16 warps), 2048 blocks.
// Stages (all via shared memory, no gmem intermediates):
//   A: q  = Wq x + bq
//   B: qk = q^T Wk (per head), pre-scaled by 1/sqrt(32)   [bk dropped:
//      constant over n => softmax-invariant]
//   C: scores -> softmax -> ctx (neighbors streamed once from DRAM,
//      second pass from L2; block-cooperative, no shuffles)
//   D: o  = Wv ctx + bv
//   E: o2 = WoP o + bo   (Wo permuted at smem load: head interleave free)
//   F/G: SE block (relu, sigmoid, scale)
//   H: learned residual gate (warp-reduce)
//   I: out = g*o3 + (1-g)*x
// =======================================================================

#define OFF_W    0        // [128][132] weight buffer (reloaded per stage)
#define OFF_QK   16896    // [32][512]  qk -> ctx (in place)
#define OFF_X    33280    // [32][128]  x (persists)
#define OFF_Q    37376    // [32][128]  q -> o -> T1
#define OFF_O2   41472    // [32][128]  o2 (SE-scaled in place)
#define OFF_S    45568    // [32][4][20] scores/attn -> gate scratch
#define OFF_G    48128    // [32] gates
#define SMEM_FLOATS 48160 // 192640 bytes

__global__ void __launch_bounds__(512, 1) k_fused(
    const float* __restrict__ x,
    const float* __restrict__ nb,
    const float* __restrict__ Wq, const float* __restrict__ bq,
    const float* __restrict__ Wk,
    const float* __restrict__ Wv, const float* __restrict__ bv,
    const float* __restrict__ Wo, const float* __restrict__ bo,
    const float* __restrict__ Wse1, const float* __restrict__ Wse2,
    const float* __restrict__ Wg, const float* __restrict__ bg,
    float* __restrict__ out)
{
    extern __shared__ float sm[];
    const int t = threadIdx.x;
    const int lane = t & 31;
    const int w = t >> 5;                 // warp 0..15
    const long rowBase = (long)blockIdx.x * 32;
    const float4* nb4 = (const float4*)nb;

    // ---------------- phase 0: Wq (padded 132) + x ----------------
    for (int i = t; i < 128*128; i += 512) {
        int j = i >> 7, c = i & 127;
        sm[OFF_W + j*132 + c] = Wq[i];
    }
    {
        const float4* xg = (const float4*)x + rowBase*32;
        float4* sx4 = (float4*)(sm + OFF_X);
        #pragma unroll
        for (int i = 0; i < 2; i++) sx4[t + 512*i] = xg[t + 512*i];
    }
    __syncthreads();

    // ---------------- stage A: q = Wq x + bq ----------------
    // warp w: rows w*2..w*2+1 ; lane: j = lane + 32*jj
    {
        const int r0 = w * 2;
        float acc[4][2];
        #pragma unroll
        for (int jj = 0; jj < 4; jj++) {
            float b = __ldg(&bq[lane + 32*jj]);
            acc[jj][0] = b; acc[jj][1] = b;
        }
        #pragma unroll 4
        for (int c4 = 0; c4 < 32; c4++) {
            float4 wv[4];
            #pragma unroll
            for (int jj = 0; jj < 4; jj++)
                wv[jj] = *(const float4*)&sm[OFF_W + (lane + 32*jj)*132 + c4*4];
            #pragma unroll
            for (int r = 0; r < 2; r++) {
                float4 xv = *(const float4*)&sm[OFF_X + (r0+r)*128 + c4*4];
                #pragma unroll
                for (int jj = 0; jj < 4; jj++) {
                    acc[jj][r] += wv[jj].x*xv.x + wv[jj].y*xv.y
                                + wv[jj].z*xv.z + wv[jj].w*xv.w;
                }
            }
        }
        __syncthreads();   // all Wq reads done before overwrite below
        #pragma unroll
        for (int jj = 0; jj < 4; jj++)
            #pragma unroll
            for (int r = 0; r < 2; r++)
                sm[OFF_Q + (r0+r)*128 + lane + 32*jj] = acc[jj][r];
    }
    // load Wk (padded) — overwrites Wq
    __syncthreads();
    for (int i = t; i < 128*128; i += 512) {
        int j = i >> 7, c = i & 127;
        sm[OFF_W + j*132 + c] = Wk[i];
    }
    __syncthreads();

    // ---------------- stage B: qk = q^T Wk, scaled ----------------
    // warp w: h = w&3, row group rg = w>>2 -> rows rg*8..rg*8+7
    // lane: c = lane + 32*k
    {
        const int h = w & 3, rg = w >> 2;
        const int rb = rg * 8;
        float acc[4][8];
        #pragma unroll
        for (int k = 0; k < 4; k++)
            #pragma unroll
            for (int rr = 0; rr < 8; rr++) acc[k][rr] = 0.0f;
        #pragma unroll 4
        for (int d = 0; d < 32; d++) {
            const int j = h*32 + d;
            float wv[4];
            #pragma unroll
            for (int k = 0; k < 4; k++) wv[k] = sm[OFF_W + j*132 + lane + 32*k];
            #pragma unroll
            for (int rr = 0; rr < 8; rr++) {
                float qv = sm[OFF_Q + (rb+rr)*128 + j];
                #pragma unroll
                for (int k = 0; k < 4; k++) acc[k][rr] += wv[k] * qv;
            }
        }
        const float sc = 0.17677669529663687f;  // 1/sqrt(32)
        #pragma unroll
        for (int rr = 0; rr < 8; rr++)
            #pragma unroll
            for (int k = 0; k < 4; k++)
                sm[OFF_QK + (rb+rr)*512 + h*128 + lane + 32*k] = acc[k][rr] * sc;
    }
    __syncthreads();

    // ---------------- stage C1: scores (+ load Wv into sW) ----------------
    for (int i = t; i < 128*128; i += 512) {
        int j = i >> 7, c = i & 127;
        sm[OFF_W + j*132 + c] = Wv[i];
    }
    for (int idx = t; idx < 640; idx += 512) {
        const int row = idx / 20;
        const int n = idx - row*20;
        const float4* nbp = nb4 + (rowBase + row)*640 + n*32;
        float a[4] = {0.f, 0.f, 0.f, 0.f};
        #pragma unroll 8
        for (int c4 = 0; c4 < 32; c4++) {
            float4 v = nbp[c4];
            #pragma unroll
            for (int h = 0; h < 4; h++) {
                float4 qh = *(const float4*)&sm[OFF_QK + row*512 + h*128 + c4*4];
                a[h] += qh.x*v.x + qh.y*v.y + qh.z*v.z + qh.w*v.w;
            }
        }
        #pragma unroll
        for (int h = 0; h < 4; h++)
            sm[OFF_S + (row*4 + h)*20 + n] = a[h];
    }
    __syncthreads();

    // ---------------- stage C2: softmax over n ----------------
    if (t < 128) {
        const int base = OFF_S + t*20;
        float m = -1e30f;
        #pragma unroll
        for (int n = 0; n < 20; n++) m = fmaxf(m, sm[base + n]);
        float s = 0.0f;
        float e[20];
        #pragma unroll
        for (int n = 0; n < 20; n++) { e[n] = __expf(sm[base + n] - m); s += e[n]; }
        float inv = 1.0f / s;
        #pragma unroll
        for (int n = 0; n < 20; n++) sm[base + n] = e[n] * inv;
    }
    __syncthreads();

    // ---------------- stage C3: ctx (overwrites qk in place) ----------------
    for (int idx = t; idx < 1024; idx += 512) {
        const int row = idx >> 5, c4 = idx & 31;
        const float4* nbp = nb4 + (rowBase + row)*640 + c4;
        float4 acc[4];
        #pragma unroll
        for (int h = 0; h < 4; h++) acc[h] = make_float4(0.f, 0.f, 0.f, 0.f);
        #pragma unroll 4
        for (int n = 0; n < 20; n++) {
            float4 v = nbp[n*32];
            #pragma unroll
            for (int h = 0; h < 4; h++) {
                float ah = sm[OFF_S + (row*4 + h)*20 + n];
                acc[h].x += ah*v.x; acc[h].y += ah*v.y;
                acc[h].z += ah*v.z; acc[h].w += ah*v.w;
            }
        }
        #pragma unroll
        for (int h = 0; h < 4; h++)
            *(float4*)&sm[OFF_QK + row*512 + h*128 + c4*4] = acc[h];
    }
    __syncthreads();

    // ---------------- stage D: o = Wv ctx + bv ----------------
    // warp w: h = w&3, rg = w>>2 -> rows rg*8.. ; lane: jsub = lane&7, rgrp = lane>>3
    // j = h*32 + jsub + 8*jj ; rows rg*8 + rgrp*2 + rr
    {
        const int h = w & 3, rg = w >> 2;
        const int jsub = lane & 7, rgrp = lane >> 3;
        const int rb = rg*8 + rgrp*2;
        float acc[4][2];
        #pragma unroll
        for (int jj = 0; jj < 4; jj++) {
            float b = __ldg(&bv[h*32 + jsub + 8*jj]);
            acc[jj][0] = b; acc[jj][1] = b;
        }
        #pragma unroll 4
        for (int c4 = 0; c4 < 32; c4++) {
            float4 wv[4];
            #pragma unroll
            for (int jj = 0; jj < 4; jj++)
                wv[jj] = *(const float4*)&sm[OFF_W + (h*32 + jsub + 8*jj)*132 + c4*4];
            #pragma unroll
            for (int r = 0; r < 2; r++) {
                float4 cv = *(const float4*)&sm[OFF_QK + (rb+r)*512 + h*128 + c4*4];
                #pragma unroll
                for (int jj = 0; jj < 4; jj++) {
                    acc[jj][r] += wv[jj].x*cv.x + wv[jj].y*cv.y
                                + wv[jj].z*cv.z + wv[jj].w*cv.w;
                }
            }
        }
        __syncthreads();   // Wv reads done; sQ (q) dead
        #pragma unroll
        for (int jj = 0; jj < 4; jj++)
            #pragma unroll
            for (int r = 0; r < 2; r++)
                sm[OFF_Q + (rb+r)*128 + h*32 + jsub + 8*jj] = acc[jj][r];
    }
    __syncthreads();

    // load WoP (permuted: out index d*4+h -> h*32+d), padded
    for (int i = t; i < 128*128; i += 512) {
        int oc = i >> 7, j2 = i & 127;
        sm[OFF_W + oc*132 + ((j2 & 3)*32 + (j2 >> 2))] = Wo[i];
    }
    __syncthreads();

    // ---------------- stage E: o2 = WoP o + bo ----------------
    {
        const int r0 = w * 2;
        float acc[4][2];
        #pragma unroll
        for (int jj = 0; jj < 4; jj++) {
            float b = __ldg(&bo[lane + 32*jj]);
            acc[jj][0] = b; acc[jj][1] = b;
        }
        #pragma unroll 4
        for (int c4 = 0; c4 < 32; c4++) {
            float4 wv[4];
            #pragma unroll
            for (int jj = 0; jj < 4; jj++)
                wv[jj] = *(const float4*)&sm[OFF_W + (lane + 32*jj)*132 + c4*4];
            #pragma unroll
            for (int r = 0; r < 2; r++) {
                float4 ov = *(const float4*)&sm[OFF_Q + (r0+r)*128 + c4*4];
                #pragma unroll
                for (int jj = 0; jj < 4; jj++) {
                    acc[jj][r] += wv[jj].x*ov.x + wv[jj].y*ov.y
                                + wv[jj].z*ov.z + wv[jj].w*ov.w;
                }
            }
        }
        #pragma unroll
        for (int jj = 0; jj < 4; jj++)
            #pragma unroll
            for (int r = 0; r < 2; r++)
                sm[OFF_O2 + (r0+r)*128 + lane + 32*jj] = acc[jj][r];
    }
    __syncthreads();

    // load SE weights into sW region: Wse1T [oc][i] @0, Wse2T [i][oc] @4096, Wg @8192
    for (int i = t; i < 32*128; i += 512) {          // Wse1 [i][oc] -> [oc][i]
        int ii = i >> 7, oc = i & 127;
        sm[OFF_W + oc*32 + ii] = Wse1[i];
    }
    for (int i = t; i < 128*32; i += 512) {          // Wse2 [oc][i] -> [i][oc]
        int oc = i >> 5, ii = i & 31;
        sm[OFF_W + 4096 + ii*128 + oc] = Wse2[i];
    }
    if (t < 256) sm[OFF_W + 8192 + t] = Wg[t];
    __syncthreads();

    // ---------------- stage F: T1 = relu(Wse1 . o2) ----------------
    // warp w: rows w*2..+1 ; lane: i
    {
        const int r0 = w * 2;
        float acc[2] = {0.f, 0.f};
        #pragma unroll 4
        for (int oc = 0; oc < 128; oc++) {
            float wv = sm[OFF_W + oc*32 + lane];
            #pragma unroll
            for (int r = 0; r < 2; r++)
                acc[r] += wv * sm[OFF_O2 + (r0+r)*128 + oc];
        }
        #pragma unroll
        for (int r = 0; r < 2; r++)
            sm[OFF_Q + (r0+r)*32 + lane] = fmaxf(acc[r], 0.0f);   // T1 in sQ
    }
    __syncthreads();

    // ---------------- stage G: se = sigmoid(Wse2 T1); o2 *= se ----------------
    {
        const int r0 = w * 2;
        float acc[4][2];
        #pragma unroll
        for (int jj = 0; jj < 4; jj++) { acc[jj][0] = 0.f; acc[jj][1] = 0.f; }
        #pragma unroll 4
        for (int i = 0; i < 32; i++) {
            float wv[4];
            #pragma unroll
            for (int jj = 0; jj < 4; jj++)
                wv[jj] = sm[OFF_W + 4096 + i*128 + lane + 32*jj];
            #pragma unroll
            for (int r = 0; r < 2; r++) {
                float tv = sm[OFF_Q + (r0+r)*32 + i];
                #pragma unroll
                for (int jj = 0; jj < 4; jj++) acc[jj][r] += wv[jj] * tv;
            }
        }
        #pragma unroll
        for (int jj = 0; jj < 4; jj++)
            #pragma unroll
            for (int r = 0; r < 2; r++)
                sm[OFF_O2 + (r0+r)*128 + lane + 32*jj] *= sigm(acc[jj][r]);
    }
    __syncthreads();

    // ---------------- stage H: gate (warp-reduce per row) ----------------
    {
        const float bgv = __ldg(bg);
        #pragma unroll
        for (int r = 0; r < 2; r++) {
            const int row = w*2 + r;
            float p = 0.0f;
            #pragma unroll
            for (int kk = 0; kk < 8; kk++) {
                int c = lane + 32*kk;
                float wgv = sm[OFF_W + 8192 + c];
                float val = (kk < 4) ? sm[OFF_X + row*128 + c]
                                     : sm[OFF_O2 + row*128 + c - 128];
                p += wgv * val;
            }
            #pragma unroll
            for (int o = 16; o; o >>= 1) p += __shfl_xor_sync(0xffffffffu, p, o);
            if (lane == 0) sm[OFF_G + row] = sigm(p + bgv);
        }
    }
    __syncthreads();

    // ---------------- stage I: out = g*o3 + (1-g)*x ----------------
    {
        float4* og = (float4*)out + rowBase*32;
        #pragma unroll
        for (int it = 0; it < 2; it++) {
            int idx = t + 512*it;
            int r = idx >> 5;
            float g = sm[OFF_G + r];
            float4 xv = *(const float4*)&sm[OFF_X + idx*4];
            float4 ov = *(const float4*)&sm[OFF_O2 + idx*4];
            float4 res;
            res.x = g*ov.x + (1.0f-g)*xv.x;
            res.y = g*ov.y + (1.0f-g)*xv.y;
            res.z = g*ov.z + (1.0f-g)*xv.z;
            res.w = g*ov.w + (1.0f-g)*xv.w;
            og[idx] = res;
        }
    }
}

// =======================================================================
extern "C" void kernel_launch(void* const* d_in, const int* in_sizes, int n_in,
                              void* d_out, int out_size)
{
    const float* x    = (const float*)d_in[0];
    const float* nb   = (const float*)d_in[1];
    const float* Wq   = (const float*)d_in[2];
    const float* bq   = (const float*)d_in[3];
    const float* Wk   = (const float*)d_in[4];
    // d_in[5] = bk : softmax-invariant, unused
    const float* Wv   = (const float*)d_in[6];
    const float* bv   = (const float*)d_in[7];
    const float* Wo   = (const float*)d_in[8];
    const float* bo   = (const float*)d_in[9];
    const float* Wse1 = (const float*)d_in[10];
    const float* Wse2 = (const float*)d_in[11];
    const float* Wg   = (const float*)d_in[12];
    const float* bg   = (const float*)d_in[13];
    float* out = (float*)d_out;

    cudaFuncSetAttribute(k_fused, cudaFuncAttributeMaxDynamicSharedMemorySize,
                         SMEM_FLOATS * 4);
    k_fused<<<2048, 512, SMEM_FLOATS * 4>>>(
        x, nb, Wq, bq, Wk, Wv, bv, Wo, bo, Wse1, Wse2, Wg, bg, out);
}